// round 17
// baseline (speedup 1.0000x reference)
#include <cuda_runtime.h>
#include <cuda_bf16.h>
#include <cstdint>

// Problem constants (B=64, D=256, H=32, W=32, K=1024)
#define TOK_N   65536
#define DDIM    256
#define KCODES  1024

// ---------------- GEMM tiling ----------------
// CTA: 128 tokens x 512 codes (half h), K=768 (hx|lx vs hc|hc|lc).
// 8 warps: wm in 0..3 (32 tokens), wn in 0..1 (64 codes). 256 threads.
// K chunks of 128 (NKC=6), n-tiles of 128 (4 per half).
#define GEMM_THREADS 256
#define NKC   6
#define NNT_G 8                 // global n-tiles (128 codes each)
#define A_ROW_BF16 512          // hx(256) | lx(256)
#define AS_BYTES (128 * A_ROW_BF16 * 2)       // 131072
#define BS_TILE_BYTES (128 * 128 * 2)          // 32768
#define GEMM_SMEM (AS_BYTES + 2*BS_TILE_BYTES + 2048)  // +cn: 198656

#define NCAND 16                // candidate slots per (half, token)

// Device-global scratch (module statics; no runtime allocation)
__device__ float g_cnorm_half[KCODES];                       // 0.5*||c||^2 (R6 reduction)
__device__ __align__(128) __nv_bfloat16 g_Asw[TOK_N * A_ROW_BF16];       // A smem image
__device__ __align__(128) __nv_bfloat16 g_Btiles[NNT_G * NKC * 128 * 128]; // B tiles
__device__ float g_cv[2 * TOK_N * NCAND];     // candidate approx values
__device__ int   g_ci[2 * TOK_N * NCAND];     // candidate indices

// ---------------------------------------------------------------------------
__device__ __forceinline__ void cp_async16(uint32_t saddr, const void* gptr) {
    asm volatile("cp.async.cg.shared.global [%0], [%1], 16;"
                 :: "r"(saddr), "l"(gptr));
}
#define CP_COMMIT()   asm volatile("cp.async.commit_group;" ::: "memory")
#define CP_WAIT_ALL() asm volatile("cp.async.wait_group 0;" ::: "memory")

__device__ __forceinline__ void cp_bulk(uint32_t dst_smem, const void* src,
                                        uint32_t bytes, uint32_t mbar) {
    asm volatile(
        "cp.async.bulk.shared::cluster.global.mbarrier::complete_tx::bytes "
        "[%0], [%1], %2, [%3];"
        :: "r"(dst_smem), "l"(src), "r"(bytes), "r"(mbar) : "memory");
}
#define MBAR_INIT(addr, cnt) \
    asm volatile("mbarrier.init.shared.b64 [%0], %1;" :: "r"(addr), "r"(cnt) : "memory")
#define MBAR_EXPECT_TX(addr, bytes) \
    asm volatile("mbarrier.arrive.expect_tx.shared.b64 _, [%0], %1;" \
                 :: "r"(addr), "r"(bytes) : "memory")
__device__ __forceinline__ void mbar_wait(uint32_t addr, uint32_t parity) {
    asm volatile(
        "{\n\t.reg .pred P;\n\t"
        "WL_%=:\n\t"
        "mbarrier.try_wait.parity.acquire.cta.shared::cta.b64 P, [%0], %1, 0x989680;\n\t"
        "@P bra.uni WD_%=;\n\t"
        "bra.uni WL_%=;\n\t"
        "WD_%=:\n\t}"
        :: "r"(addr), "r"(parity) : "memory");
}

__device__ __forceinline__ void ldsm4(uint32_t* r, uint32_t addr) {
    asm volatile("ldmatrix.sync.aligned.m8n8.x4.shared.b16 {%0,%1,%2,%3}, [%4];"
                 : "=r"(r[0]), "=r"(r[1]), "=r"(r[2]), "=r"(r[3]) : "r"(addr));
}
__device__ __forceinline__ void mma16816(float* c, const uint32_t* a,
                                         uint32_t b0, uint32_t b1) {
    asm volatile(
        "mma.sync.aligned.m16n8k16.row.col.f32.bf16.bf16.f32 "
        "{%0,%1,%2,%3}, {%4,%5,%6,%7}, {%8,%9}, {%0,%1,%2,%3};"
        : "+f"(c[0]), "+f"(c[1]), "+f"(c[2]), "+f"(c[3])
        : "r"(a[0]), "r"(a[1]), "r"(a[2]), "r"(a[3]), "r"(b0), "r"(b1));
}

// ---------------------------------------------------------------------------
// Prep codebook: g_cnorm_half via the EXACT R6 reduction (rescore depends on
// bit-identical values), plus pre-swizzled bf16-split B tiles.
// B row (code k) over K=768: [hc(d) | hc(d) | lc(d)].
// Tile layout: [nt(8)][kc(6)][n(128)][128 k-bf16], unit-swizzle u^=(n&7).
// ---------------------------------------------------------------------------
__global__ void __launch_bounds__(256) vq_prep(const float* __restrict__ cb) {
    int k = blockIdx.x;
    int d = threadIdx.x;
    float v = cb[k * DDIM + d];

    __shared__ float red[256];
    red[d] = v * v;
    __syncthreads();
    #pragma unroll
    for (int s = 128; s > 0; s >>= 1) {
        if (d < s) red[d] += red[d + s];
        __syncthreads();
    }
    if (d == 0) g_cnorm_half[k] = 0.5f * red[0];

    __nv_bfloat16 hc = __float2bfloat16_rn(v);
    __nv_bfloat16 lc = __float2bfloat16_rn(v - __bfloat162float(hc));
    int nt = k >> 7;
    int n  = k & 127;
    #pragma unroll
    for (int seg = 0; seg < 3; seg++) {
        int j = seg * 256 + d;                 // global K index 0..767
        __nv_bfloat16 val = (seg == 2) ? lc : hc;
        int kc = j >> 7;
        int kk = j & 127;
        int u  = (kk >> 3) ^ (n & 7);          // swizzled 16B unit (0..15)
        g_Btiles[(((nt * NKC + kc) * 128 + n) * 128) + u * 8 + (kk & 7)] = val;
    }
}

// ---------------------------------------------------------------------------
// Prep x: bf16 split into pre-swizzled A smem images.
// Per 128-token block: row m = [hx(0..255) | lx(0..255)], 512 bf16 = 64 units,
// unit-swizzle u^=(m&7). One 128KB bulk copy per GEMM CTA later.
// ---------------------------------------------------------------------------
__global__ void __launch_bounds__(512) vq_xprep(const float* __restrict__ x) {
    extern __shared__ float xs[];              // [256 d][128 m]
    const int tid = threadIdx.x;
    const int mb  = blockIdx.x;
    const int m0  = mb * 128;
    const int b   = m0 >> 10;
    const int hw0 = m0 & 1023;
    const float* xbase = x + (long long)b * (DDIM * 1024) + hw0;

    const uint32_t xs_u = (uint32_t)__cvta_generic_to_shared(xs);
    #pragma unroll 4
    for (int f = tid; f < DDIM * 128 / 4; f += 512) {
        int d  = f >> 5;
        int m4 = f & 31;
        cp_async16(xs_u + (uint32_t)(d * 128 + m4 * 4) * 4,
                   xbase + d * 1024 + m4 * 4);
    }
    CP_COMMIT();
    CP_WAIT_ALL();
    __syncthreads();

    const int m = tid >> 2;                    // 0..127
    const int p = tid & 3;
    uint4* dst = reinterpret_cast<uint4*>(&g_Asw[(long long)(m0 + m) * A_ROW_BF16]);
    #pragma unroll
    for (int uu = 0; uu < 16; uu++) {
        int u = uu * 4 + p;                    // logical unit 0..63
        __nv_bfloat16 vals[8];
        #pragma unroll
        for (int e = 0; e < 8; e++) {
            int j = u * 8 + e;                 // col 0..511
            if (j < 256) {
                vals[e] = __float2bfloat16_rn(xs[j * 128 + m]);
            } else {
                float xv = xs[(j - 256) * 128 + m];
                __nv_bfloat16 hv = __float2bfloat16_rn(xv);
                vals[e] = __float2bfloat16_rn(xv - __bfloat162float(hv));
            }
        }
        dst[u ^ (m & 7)] = *reinterpret_cast<uint4*>(vals);
    }
}

// ---------------------------------------------------------------------------
// Approx GEMM: 128 tokens x 512 codes (half h) per CTA, K=768 bf16, fp32 acc.
// Keeps per-(thread, token-row) top-2 approx (score - 0.5||c||^2) candidates.
// Each thread covers a DISJOINT 64-code subset per token row, so the global
// best is always some thread's approx-top-1 -> always emitted.
// ---------------------------------------------------------------------------
__global__ void __launch_bounds__(GEMM_THREADS, 1) vq_gemm() {
    extern __shared__ char smem[];
    const uint32_t smA = (uint32_t)__cvta_generic_to_shared(smem);
    const uint32_t smB = smA + AS_BYTES;
    float* cn_s = reinterpret_cast<float*>(smem + AS_BYTES + 2 * BS_TILE_BYTES);
    __shared__ unsigned long long s_mbar[3];   // A, B0, B1
    const uint32_t mbA = (uint32_t)__cvta_generic_to_shared(s_mbar);

    const int tid  = threadIdx.x;
    const int lane = tid & 31;
    const int wid  = tid >> 5;
    const int wm   = wid & 3;                  // token group (32)
    const int wn   = wid >> 2;                 // code group (64)

    const int mb = blockIdx.x >> 1;
    const int h  = blockIdx.x & 1;

    if (tid == 0) {
        MBAR_INIT(mbA, 1);
        MBAR_INIT(mbA + 8, 1);
        MBAR_INIT(mbA + 16, 1);
    }
    __syncthreads();
    if (tid == 0) {
        const char* asrc = reinterpret_cast<const char*>(
            &g_Asw[(long long)mb * 128 * A_ROW_BF16]);
        MBAR_EXPECT_TX(mbA, AS_BYTES);
        #pragma unroll
        for (int q = 0; q < 4; q++)
            cp_bulk(smA + q * 32768, asrc + q * 32768, 32768, mbA);
        const int ntg0 = h * 4;
        MBAR_EXPECT_TX(mbA + 8, BS_TILE_BYTES);
        cp_bulk(smB, &g_Btiles[(ntg0 * NKC + 0) * 16384], BS_TILE_BYTES, mbA + 8);
        MBAR_EXPECT_TX(mbA + 16, BS_TILE_BYTES);
        cp_bulk(smB + BS_TILE_BYTES, &g_Btiles[(ntg0 * NKC + 1) * 16384],
                BS_TILE_BYTES, mbA + 16);
    }
    for (int i = tid; i < 512; i += GEMM_THREADS)
        cn_s[i] = g_cnorm_half[h * 512 + i];
    __syncthreads();                            // cn visible
    mbar_wait(mbA, 0);                          // A slab resident

    float tv[4][2];
    int   ti[4][2];
    #pragma unroll
    for (int r = 0; r < 4; r++) {
        tv[r][0] = tv[r][1] = -3.0e38f;
        ti[r][0] = ti[r][1] = 0;
    }

    for (int nt = 0; nt < 4; ++nt) {
        float acc[2][8][4];
        #pragma unroll
        for (int mt = 0; mt < 2; mt++)
            #pragma unroll
            for (int j = 0; j < 8; j++)
                #pragma unroll
                for (int e = 0; e < 4; e++) acc[mt][j][e] = 0.f;

        for (int kc = 0; kc < NKC; ++kc) {
            const int idx = nt * NKC + kc;      // 0..23
            const uint32_t mbB = mbA + 8 + (idx & 1) * 8;
            mbar_wait(mbB, (idx >> 1) & 1);
            const uint32_t bsb = smB + (idx & 1) * BS_TILE_BYTES;
            // A column base (bf16 units): kc 0,1 -> hx; 2,3 -> lx; 4,5 -> hx
            const int au0 = ((kc < 4) ? kc : (kc - 4)) * 16;

            #pragma unroll
            for (int ks = 0; ks < 8; ks++) {
                uint32_t a[2][4];
                #pragma unroll
                for (int mt = 0; mt < 2; mt++) {
                    int row = wm * 32 + mt * 16 + (lane & 15);
                    int u   = au0 + ks * 2 + (lane >> 4);
                    ldsm4(a[mt], smA + (uint32_t)(row * 64 + (u ^ (row & 7))) * 16);
                }
                uint32_t bf[4][4];
                #pragma unroll
                for (int p = 0; p < 4; p++) {
                    int row = wn * 64 + p * 16 + (lane & 15);
                    int u   = ks * 2 + (lane >> 4);
                    ldsm4(bf[p], bsb + (uint32_t)(row * 16 + (u ^ (row & 7))) * 16);
                }
                #pragma unroll
                for (int mt = 0; mt < 2; mt++)
                    #pragma unroll
                    for (int p = 0; p < 4; p++) {
                        mma16816(acc[mt][2 * p],     a[mt], bf[p][0], bf[p][2]);
                        mma16816(acc[mt][2 * p + 1], a[mt], bf[p][1], bf[p][3]);
                    }
            }

            __syncthreads();                    // all warps done with buf idx&1
            if (tid == 0 && idx + 2 < 4 * NKC) {
                const int i2 = idx + 2;
                const int tile = (h * 4 + (i2 / NKC)) * NKC + (i2 % NKC);
                MBAR_EXPECT_TX(mbB, BS_TILE_BYTES);
                cp_bulk(smB + (idx & 1) * BS_TILE_BYTES,
                        &g_Btiles[tile * 16384], BS_TILE_BYTES, mbB);
            }
        }

        // n-tile epilogue: bias + top-2 pool insert (ascending n per pool)
        #pragma unroll
        for (int mt = 0; mt < 2; mt++) {
            #pragma unroll
            for (int j = 0; j < 8; j++) {
                int nn  = nt * 128 + wn * 64 + (j >> 1) * 16 + (j & 1) * 8
                        + (lane & 3) * 2;
                float c0 = cn_s[nn], c1 = cn_s[nn + 1];
                int n = h * 512 + nn;
                #pragma unroll
                for (int rh = 0; rh < 2; rh++) {
                    int pr = mt * 2 + rh;
                    float v0 = acc[mt][j][rh * 2]     - c0;
                    float v1 = acc[mt][j][rh * 2 + 1] - c1;
                    if (v0 > tv[pr][0]) { tv[pr][1]=tv[pr][0]; ti[pr][1]=ti[pr][0];
                                          tv[pr][0]=v0; ti[pr][0]=n; }
                    else if (v0 > tv[pr][1]) { tv[pr][1]=v0; ti[pr][1]=n; }
                    if (v1 > tv[pr][0]) { tv[pr][1]=tv[pr][0]; ti[pr][1]=ti[pr][0];
                                          tv[pr][0]=v1; ti[pr][0]=n+1; }
                    else if (v1 > tv[pr][1]) { tv[pr][1]=v1; ti[pr][1]=n+1; }
                }
            }
        }
    }

    // Emit candidates. Token row = (wm, mt, rh, lane>>2); slot must be unique
    // per thread covering that row: (wn, lane&3) -> 8 threads x top-2 = 16.
    // (R16 bug: wn was omitted -> two warps raced on the same 8 slots.)
    #pragma unroll
    for (int mt = 0; mt < 2; mt++)
        #pragma unroll
        for (int rh = 0; rh < 2; rh++) {
            int pr = mt * 2 + rh;
            int m_g = mb * 128 + wm * 32 + mt * 16 + rh * 8 + (lane >> 2);
            long long base = ((long long)h * TOK_N + m_g) * NCAND
                           + wn * 8 + (lane & 3) * 2;
            g_cv[base] = tv[pr][0];     g_ci[base] = ti[pr][0];
            g_cv[base + 1] = tv[pr][1]; g_ci[base + 1] = ti[pr][1];
        }
}

// ---------------------------------------------------------------------------
// Rescore top-4 of 32 candidates exactly (R6 contract: sequential fmaf over
// d=0..255, then -0.5||c||^2), pick argmax with lowest-index tie-break,
// gather + write both outputs (raw-reshape: out[n*256+d]).
// ---------------------------------------------------------------------------
__global__ void __launch_bounds__(256) vq_rescore(const float* __restrict__ x,
                                                  const float* __restrict__ cb,
                                                  float* __restrict__ out,
                                                  int halfElems) {
    extern __shared__ float xs[];              // [256 d][128 m]
    __shared__ int fidx[128];
    const int tid = threadIdx.x;
    const int mb  = blockIdx.x;
    const int m0  = mb * 128;
    const int b   = m0 >> 10;
    const int hw0 = m0 & 1023;
    const float* xbase = x + (long long)b * (DDIM * 1024) + hw0;

    const uint32_t xs_u = (uint32_t)__cvta_generic_to_shared(xs);
    #pragma unroll 4
    for (int f = tid; f < DDIM * 128 / 4; f += 256) {
        int d  = f >> 5;
        int m4 = f & 31;
        cp_async16(xs_u + (uint32_t)(d * 128 + m4 * 4) * 4,
                   xbase + d * 1024 + m4 * 4);
    }
    CP_COMMIT();
    CP_WAIT_ALL();
    __syncthreads();

    if (tid < 128) {
        const int m = m0 + tid;
        float cv[2 * NCAND]; int ci[2 * NCAND];
        #pragma unroll
        for (int hh = 0; hh < 2; hh++)
            #pragma unroll
            for (int e = 0; e < NCAND; e++) {
                long long s = ((long long)hh * TOK_N + m) * NCAND + e;
                cv[hh * NCAND + e] = g_cv[s];
                ci[hh * NCAND + e] = g_ci[s];
            }
        // select top-4 by (value desc, index asc)
        int sel[4];
        unsigned used = 0;
        #pragma unroll
        for (int r = 0; r < 4; r++) {
            float bv = -3.4e38f; int bi = 0x7fffffff; int bj = 0;
            #pragma unroll
            for (int e = 0; e < 2 * NCAND; e++) {
                bool ok = !((used >> e) & 1);
                if (ok && (cv[e] > bv || (cv[e] == bv && ci[e] < bi))) {
                    bv = cv[e]; bi = ci[e]; bj = e;
                }
            }
            used |= 1u << bj;
            sel[r] = bi;
        }
        // sort ascending index (4 elems)
        #pragma unroll
        for (int a = 0; a < 3; a++)
            #pragma unroll
            for (int bb = 0; bb < 3 - a; bb++)
                if (sel[bb] > sel[bb + 1]) { int t = sel[bb]; sel[bb] = sel[bb+1]; sel[bb+1] = t; }

        // exact rescore: 4 independent sequential fma chains (ILP across cands)
        const float* c0 = cb + (long long)sel[0] * DDIM;
        const float* c1 = cb + (long long)sel[1] * DDIM;
        const float* c2 = cb + (long long)sel[2] * DDIM;
        const float* c3 = cb + (long long)sel[3] * DDIM;
        float s0 = 0.f, s1 = 0.f, s2 = 0.f, s3 = 0.f;
        #pragma unroll 8
        for (int d = 0; d < DDIM; d++) {
            float xv = xs[d * 128 + tid];
            s0 = __fmaf_rn(xv, c0[d], s0);
            s1 = __fmaf_rn(xv, c1[d], s1);
            s2 = __fmaf_rn(xv, c2[d], s2);
            s3 = __fmaf_rn(xv, c3[d], s3);
        }
        s0 -= g_cnorm_half[sel[0]];
        s1 -= g_cnorm_half[sel[1]];
        s2 -= g_cnorm_half[sel[2]];
        s3 -= g_cnorm_half[sel[3]];
        float bv = s0; int bi = sel[0];
        if (s1 > bv) { bv = s1; bi = sel[1]; }   // ascending index: strict '>'
        if (s2 > bv) { bv = s2; bi = sel[2]; }
        if (s3 > bv) { bv = s3; bi = sel[3]; }
        fidx[tid] = bi;
    }
    __syncthreads();

    const float4* cb4 = reinterpret_cast<const float4*>(cb);
    float4* o1 = reinterpret_cast<float4*>(out);
    float4* o2 = reinterpret_cast<float4*>(out + halfElems);
    #pragma unroll 4
    for (int f = tid; f < 128 * (DDIM / 4); f += 256) {
        int m  = f >> 6;
        int d4 = f & 63;
        float4 v = cb4[fidx[m] * (DDIM / 4) + d4];
        long long o = (long long)(m0 + m) * (DDIM / 4) + d4;
        o1[o] = v;
        o2[o] = v;
    }
}

// ---------------------------------------------------------------------------
extern "C" void kernel_launch(void* const* d_in, const int* in_sizes, int n_in,
                              void* d_out, int out_size) {
    const float* x  = reinterpret_cast<const float*>(d_in[0]);
    const float* cb = reinterpret_cast<const float*>(d_in[1]);
    if (n_in >= 2 && in_sizes[0] == KCODES * DDIM && in_sizes[1] != KCODES * DDIM) {
        const float* tmp = x; x = cb; cb = tmp;
    }
    float* out = reinterpret_cast<float*>(d_out);
    int halfElems = out_size / 2;

    cudaFuncSetAttribute(vq_xprep, cudaFuncAttributeMaxDynamicSharedMemorySize, 131072);
    cudaFuncSetAttribute(vq_gemm, cudaFuncAttributeMaxDynamicSharedMemorySize, GEMM_SMEM);
    cudaFuncSetAttribute(vq_rescore, cudaFuncAttributeMaxDynamicSharedMemorySize, 131072);

    vq_prep<<<KCODES, 256>>>(cb);
    vq_xprep<<<TOK_N / 128, 512, 131072>>>(x);
    vq_gemm<<<(TOK_N / 128) * 2, GEMM_THREADS, GEMM_SMEM>>>();
    vq_rescore<<<TOK_N / 128, 256, 131072>>>(x, cb, out, halfElems);
}